// round 6
// baseline (speedup 1.0000x reference)
#include <cuda_runtime.h>

#define NBANDS 31
#define NB     16
#define NT     1000
#define NF     257
#define NO     128
#define MAXC   34
#define KTOT   536      // sum of roundup4(2*bw)
#define TT     8        // time tile per block
#define NCH    8        // stats chunks per (b,band)
#define OUTW   (NO * NBANDS)   // 3968

__constant__ int c_bw[NBANDS] = {
    2,3,3,3,3,3,3,3,3,3,3,
    8,8,8,8,8,8,8,8,8,8,8,8,
    16,16,16,16,16,16,16,17
};
__constant__ int c_kal[NBANDS] = {
    0,4,12,20,28,36,44,52,60,68,76,
    84,100,116,132,148,164,180,196,212,228,244,260,
    276,308,340,372,404,436,468,500
};
__constant__ int c_f0[NBANDS] = {
    0,2,5,8,11,14,17,20,23,26,29,
    32,40,48,56,64,72,80,88,96,104,112,120,
    128,144,160,176,192,208,224,240
};
// 16 band-groups (one warp each); padded-C sums 32..40
__constant__ int c_gs[17] = {0,1,2,3,4,5,6,7,8,10,12,14,16,18,21,26,31};
__constant__ int c_gb[31] = {
    30,
    23,24,25,26,27,28,29,
    11,12, 13,14, 15,16, 17,18, 19,20,
    21,22,0,
    1,2,3,4,5,
    6,7,8,9,10
};
// k-slots that are zero-padding (C=6 bands pad 2 each, band30 pads 2)
__constant__ int c_pad[22] = {
    10,11,18,19,26,27,34,35,42,43,50,51,58,59,66,67,74,75,82,83,534,535
};

// static scratch
__device__ float  d_A2[NB * KTOT];
__device__ float  d_B2[NB * KTOT];
__device__ float  d_w2[KTOT * NO];            // interleaved-o weight rows
__device__ float  d_bp[NBANDS * NO];          // interleaved-o bias
__device__ float2 d_ps[NB * NBANDS * NCH];    // partial (sum, sumsq)

// closed-form global-k index for frequency f (component 0)
__device__ __forceinline__ int kg_of_f(int f)
{
    if (f >= 32) return 2 * f + 20;
    if (f >= 2)  return 2 * f - 2 + 2 * ((f + 1) / 3);
    return 2 * f;
}

__device__ __forceinline__ float2 u2f(unsigned long long u)
{
    float2 r;
    asm("mov.b64 {%0,%1}, %2;" : "=f"(r.x), "=f"(r.y) : "l"(u));
    return r;
}

// ---------------------------------------------------------------------------
// Stats stage 1: partial sums over a t-chunk of x[b, f0:f0+bw, :, :]
// ---------------------------------------------------------------------------
__global__ __launch_bounds__(256)
void stats1(const float* __restrict__ x)
{
    const int b    = blockIdx.x;
    const int band = blockIdx.y;
    const int ch   = blockIdx.z;
    const int bw   = c_bw[band];
    const float4* p = (const float4*)(x + (size_t)(b * NF + c_f0[band]) * (NT * 2));
    const int nv = bw * NT / 2;
    const int i0 = (int)((long long)nv * ch / NCH);
    const int i1 = (int)((long long)nv * (ch + 1) / NCH);

    float4 a1 = make_float4(0.f, 0.f, 0.f, 0.f);
    float4 a2 = a1;
    for (int i = i0 + threadIdx.x; i < i1; i += 256) {
        float4 v = p[i];
        a1.x += v.x; a1.y += v.y; a1.z += v.z; a1.w += v.w;
        a2.x = fmaf(v.x, v.x, a2.x); a2.y = fmaf(v.y, v.y, a2.y);
        a2.z = fmaf(v.z, v.z, a2.z); a2.w = fmaf(v.w, v.w, a2.w);
    }
    float s  = (a1.x + a1.y) + (a1.z + a1.w);
    float s2 = (a2.x + a2.y) + (a2.z + a2.w);
    for (int off = 16; off; off >>= 1) {
        s  += __shfl_down_sync(0xFFFFFFFFu, s,  off);
        s2 += __shfl_down_sync(0xFFFFFFFFu, s2, off);
    }
    __shared__ float sh0[8], sh1[8];
    const int w = threadIdx.x >> 5, l = threadIdx.x & 31;
    if (l == 0) { sh0[w] = s; sh1[w] = s2; }
    __syncthreads();
    if (threadIdx.x == 0) {
        float ts = 0.f, ts2 = 0.f;
        #pragma unroll
        for (int i = 0; i < 8; i++) { ts += sh0[i]; ts2 += sh1[i]; }
        d_ps[(b * NBANDS + band) * NCH + ch] = make_float2(ts, ts2);
    }
}

// ---------------------------------------------------------------------------
// Stats stage 2: deterministic fp64 combine; fold GN into per-k affine A, B.
// ---------------------------------------------------------------------------
__global__ __launch_bounds__(64)
void stats2(const float* __restrict__ gnw, const float* __restrict__ gnb)
{
    const int b    = blockIdx.x;
    const int band = blockIdx.y;
    const int bw   = c_bw[band];
    const int n    = bw * NT * 2;

    __shared__ float sh_mean, sh_inv;
    if (threadIdx.x == 0) {
        double ts = 0.0, ts2 = 0.0;
        #pragma unroll
        for (int i = 0; i < NCH; i++) {
            float2 v = d_ps[(b * NBANDS + band) * NCH + i];
            ts += (double)v.x; ts2 += (double)v.y;
        }
        double mean = ts / n;
        double var  = ts2 / n - mean * mean;
        sh_mean = (float)mean;
        sh_inv  = rsqrtf((float)var + 1e-5f);
    }
    __syncthreads();

    const int c = 2 * bw;
    if (threadIdx.x < c) {
        float gw = gnw[band * MAXC + threadIdx.x];
        float gb = gnb[band * MAXC + threadIdx.x];
        float A  = gw * sh_inv;
        int   kg = c_kal[band] + threadIdx.x;
        d_A2[b * KTOT + kg] = A;
        d_B2[b * KTOT + kg] = gb - A * sh_mean;
    }
}

// ---------------------------------------------------------------------------
// Weight/bias prep, interleaved-o: row position 4l+j holds o = l + {0,64,32,96}[j].
// ---------------------------------------------------------------------------
__global__ __launch_bounds__(256)
void prep_w(const float* __restrict__ fcw, const float* __restrict__ fcb)
{
    const int band = blockIdx.x;
    const int C    = 2 * c_bw[band];
    const int kp   = (C + 3) & ~3;
    const int kal  = c_kal[band];
    for (int idx = threadIdx.x; idx < kp * NO; idx += blockDim.x) {
        const int k = idx >> 7;
        const int p = idx & 127;
        const int l = p >> 2;
        const int j = p & 3;
        const int o = l + (j & 1) * 64 + (j >> 1) * 32;   // {0,64,32,96}
        d_w2[(kal + k) * NO + p] = (k < C) ? fcw[(band * NO + o) * MAXC + k] : 0.0f;
    }
    if (threadIdx.x < NO) {
        const int p = threadIdx.x;
        const int l = p >> 2;
        const int j = p & 3;
        const int o = l + (j & 1) * 64 + (j >> 1) * 32;
        d_bp[band * NO + p] = fcb[band * NO + o];
    }
}

// ---------------------------------------------------------------------------
// Fused kernel, TT=8 (weights register-resident across 8 t's), occ 1.
// y duplicated {y,y} pairs for f32x2 broadcast; s_out in exact output order;
// final copy via cp.async.bulk smem -> gmem.
// ---------------------------------------------------------------------------
#define SOUT_F   (TT * OUTW)                  // 31744 floats (126976 B)
#define SY_F     (TT * KTOT * 2)              // 8576 floats
#define SMEM_F   (SOUT_F + SY_F + 2 * KTOT)   // 41392 floats = 165568 B

#define FMA2(acc, wv, yv) \
    asm("fma.rn.f32x2 %0, %1, %2, %0;" : "+l"(acc) : "l"(wv), "l"(yv));

__global__ __launch_bounds__(512, 1)
void fused_kernel(const float* __restrict__ x,
                  float* __restrict__ out)
{
    extern __shared__ float sm[];
    float* s_out = sm;                        // [t][OUTW] exact output order
    float* s_y2  = sm + SOUT_F;               // [t][KTOT] duplicated pairs
    float* s_A   = sm + SOUT_F + SY_F;
    float* s_B   = s_A + KTOT;

    const int b   = blockIdx.y;
    const int t0  = blockIdx.x * TT;
    const int tid = threadIdx.x;

    for (int i = tid; i < KTOT; i += 512) {
        s_A[i] = d_A2[b * KTOT + i];
        s_B[i] = d_B2[b * KTOT + i];
    }
    // zero only the 22 padded k-slots (w-pad is 0, but 0*uninit = NaN)
    if (tid < 22 * TT) {
        const int t    = tid / 22;
        const int slot = c_pad[tid - 22 * t];
        *(float2*)&s_y2[(t * KTOT + slot) * 2] = make_float2(0.f, 0.f);
    }
    __syncthreads();

    // y-build: y[t][kg] = A*x + B, duplicated pair written with one STS.64
    for (int idx = tid; idx < NF * 4; idx += 512) {
        const int f = idx >> 2;
        const int q = idx & 3;                // q -> t-pair (2q, 2q+1)
        const float4 v = *(const float4*)(x + ((size_t)(b * NF + f) * NT + t0) * 2 + q * 4);
        const int kg = kg_of_f(f);
        const int ta = 2 * q, tb = 2 * q + 1;
        const float A0 = s_A[kg], B0 = s_B[kg];
        const float A1 = s_A[kg + 1], B1 = s_B[kg + 1];
        float y;
        y = fmaf(A0, v.x, B0);
        *(float2*)&s_y2[(ta * KTOT + kg    ) * 2] = make_float2(y, y);
        y = fmaf(A1, v.y, B1);
        *(float2*)&s_y2[(ta * KTOT + kg + 1) * 2] = make_float2(y, y);
        y = fmaf(A0, v.z, B0);
        *(float2*)&s_y2[(tb * KTOT + kg    ) * 2] = make_float2(y, y);
        y = fmaf(A1, v.w, B1);
        *(float2*)&s_y2[(tb * KTOT + kg + 1) * 2] = make_float2(y, y);
    }
    __syncthreads();

    const int lane = tid & 31;
    const int warp = tid >> 5;     // = band group

    for (int bi = c_gs[warp]; bi < c_gs[warp + 1]; bi++) {
        const int band = c_gb[bi];
        const int kal  = c_kal[band];
        const int kcnt = (2 * c_bw[band] + 3) & ~3;
        const ulonglong2* wp = (const ulonglong2*)(d_w2 + (size_t)kal * NO) + lane;

        unsigned long long acc[TT][2];
        {
            ulonglong2 bz = __ldg((const ulonglong2*)(d_bp + band * NO) + lane);
            #pragma unroll
            for (int t = 0; t < TT; t++) { acc[t][0] = bz.x; acc[t][1] = bz.y; }
        }

        const unsigned long long* yb =
            (const unsigned long long*)s_y2 + kal;   // index: t*KTOT + k

        for (int k = 0; k < kcnt; k += 4) {
            const ulonglong2 w0 = __ldg(wp + (k + 0) * 32);
            const ulonglong2 w1 = __ldg(wp + (k + 1) * 32);
            const ulonglong2 w2 = __ldg(wp + (k + 2) * 32);
            const ulonglong2 w3 = __ldg(wp + (k + 3) * 32);
            #pragma unroll
            for (int t = 0; t < TT; t++) {
                const ulonglong2 ya = *(const ulonglong2*)(yb + t * KTOT + k);
                const ulonglong2 yc = *(const ulonglong2*)(yb + t * KTOT + k + 2);
                FMA2(acc[t][0], w0.x, ya.x) FMA2(acc[t][1], w0.y, ya.x)
                FMA2(acc[t][0], w1.x, ya.y) FMA2(acc[t][1], w1.y, ya.y)
                FMA2(acc[t][0], w2.x, yc.x) FMA2(acc[t][1], w2.y, yc.x)
                FMA2(acc[t][0], w3.x, yc.y) FMA2(acc[t][1], w3.y, yc.y)
            }
        }

        // conflict-free scalar STS: bank = (31*lane + band) mod 32 (distinct/lane)
        #pragma unroll
        for (int t = 0; t < TT; t++) {
            float* so = s_out + t * OUTW + 31 * lane + band;
            float2 pa = u2f(acc[t][0]);     // (o=l,    o=l+64)
            float2 pb = u2f(acc[t][1]);     // (o=l+32, o=l+96)
            so[0]    = pa.x;
            so[1984] = pa.y;                // 31*64
            so[992]  = pb.x;                // 31*32
            so[2976] = pb.y;                // 31*96
        }
    }
    __syncthreads();

    // async bulk copy smem -> gmem (contiguous 126976 B), issued by one thread
    if (tid == 0) {
        unsigned int saddr;
        asm("{ .reg .u64 t; cvta.to.shared.u64 t, %1; cvt.u32.u64 %0, t; }"
            : "=r"(saddr) : "l"(s_out));
        float* dst = out + (size_t)(b * NT + t0) * OUTW;
        asm volatile("fence.proxy.async.shared::cta;" ::: "memory");
        asm volatile("cp.async.bulk.global.shared::cta.bulk_group [%0], [%1], %2;"
                     :: "l"(dst), "r"(saddr), "r"(SOUT_F * 4) : "memory");
        asm volatile("cp.async.bulk.commit_group;" ::: "memory");
        asm volatile("cp.async.bulk.wait_group.read 0;" ::: "memory");
    }
}

// ---------------------------------------------------------------------------
extern "C" void kernel_launch(void* const* d_in, const int* in_sizes, int n_in,
                              void* d_out, int out_size)
{
    const float* x   = (const float*)d_in[0];
    const float* gnw = (const float*)d_in[1];
    const float* gnb = (const float*)d_in[2];
    const float* fcw = (const float*)d_in[3];
    const float* fcb = (const float*)d_in[4];
    float* out = (float*)d_out;

    const int smem_bytes = SMEM_F * 4;
    cudaFuncSetAttribute(fused_kernel,
                         cudaFuncAttributeMaxDynamicSharedMemorySize, smem_bytes);

    stats1<<<dim3(NB, NBANDS, NCH), 256>>>(x);
    stats2<<<dim3(NB, NBANDS), 64>>>(gnw, gnb);
    prep_w<<<NBANDS, 256>>>(fcw, fcb);
    fused_kernel<<<dim3(NT / TT, NB), 512, smem_bytes>>>(x, out);
}

// round 7
// speedup vs baseline: 1.0914x; 1.0914x over previous
#include <cuda_runtime.h>

#define NBANDS 31
#define NB     16
#define NT     1000
#define NF     257
#define NO     128
#define MAXC   34
#define KTOT   536      // sum of roundup4(2*bw)
#define TT     4        // time tile per block
#define NCH    8        // stats chunks per (b,band)
#define OUTW   (NO * NBANDS)   // 3968

__constant__ int c_bw[NBANDS] = {
    2,3,3,3,3,3,3,3,3,3,3,
    8,8,8,8,8,8,8,8,8,8,8,8,
    16,16,16,16,16,16,16,17
};
__constant__ int c_kal[NBANDS] = {
    0,4,12,20,28,36,44,52,60,68,76,
    84,100,116,132,148,164,180,196,212,228,244,260,
    276,308,340,372,404,436,468,500
};
__constant__ int c_f0[NBANDS] = {
    0,2,5,8,11,14,17,20,23,26,29,
    32,40,48,56,64,72,80,88,96,104,112,120,
    128,144,160,176,192,208,224,240
};
// 16 band-groups (one warp each); padded-C sums 32..40
__constant__ int c_gs[17] = {0,1,2,3,4,5,6,7,8,10,12,14,16,18,21,26,31};
__constant__ int c_gb[31] = {
    30,
    23,24,25,26,27,28,29,
    11,12, 13,14, 15,16, 17,18, 19,20,
    21,22,0,
    1,2,3,4,5,
    6,7,8,9,10
};
// k-slots that are zero-padding (C=6 bands pad 2 each, band30 pads 2)
__constant__ int c_pad[22] = {
    10,11,18,19,26,27,34,35,42,43,50,51,58,59,66,67,74,75,82,83,534,535
};

// static scratch
__device__ float  d_A2[NB * KTOT];
__device__ float  d_B2[NB * KTOT];
__device__ float  d_w2[KTOT * NO];            // interleaved-o weight rows
__device__ float  d_bp[NBANDS * NO];          // interleaved-o bias
__device__ float2 d_ps[NB * NBANDS * NCH];    // partial (sum, sumsq)

// closed-form global-k index for frequency f (component 0)
__device__ __forceinline__ int kg_of_f(int f)
{
    if (f >= 32) return 2 * f + 20;
    if (f >= 2)  return 2 * f - 2 + 2 * ((f + 1) / 3);
    return 2 * f;
}

__device__ __forceinline__ float2 u2f(unsigned long long u)
{
    float2 r;
    asm("mov.b64 {%0,%1}, %2;" : "=f"(r.x), "=f"(r.y) : "l"(u));
    return r;
}

// ---------------------------------------------------------------------------
// Stats stage 1: partial sums over a t-chunk of x[b, f0:f0+bw, :, :]
// ---------------------------------------------------------------------------
__global__ __launch_bounds__(256)
void stats1(const float* __restrict__ x)
{
    const int b    = blockIdx.x;
    const int band = blockIdx.y;
    const int ch   = blockIdx.z;
    const int bw   = c_bw[band];
    const float4* p = (const float4*)(x + (size_t)(b * NF + c_f0[band]) * (NT * 2));
    const int nv = bw * NT / 2;
    const int i0 = (int)((long long)nv * ch / NCH);
    const int i1 = (int)((long long)nv * (ch + 1) / NCH);

    float4 a1 = make_float4(0.f, 0.f, 0.f, 0.f);
    float4 a2 = a1;
    for (int i = i0 + threadIdx.x; i < i1; i += 256) {
        float4 v = p[i];
        a1.x += v.x; a1.y += v.y; a1.z += v.z; a1.w += v.w;
        a2.x = fmaf(v.x, v.x, a2.x); a2.y = fmaf(v.y, v.y, a2.y);
        a2.z = fmaf(v.z, v.z, a2.z); a2.w = fmaf(v.w, v.w, a2.w);
    }
    float s  = (a1.x + a1.y) + (a1.z + a1.w);
    float s2 = (a2.x + a2.y) + (a2.z + a2.w);
    for (int off = 16; off; off >>= 1) {
        s  += __shfl_down_sync(0xFFFFFFFFu, s,  off);
        s2 += __shfl_down_sync(0xFFFFFFFFu, s2, off);
    }
    __shared__ float sh0[8], sh1[8];
    const int w = threadIdx.x >> 5, l = threadIdx.x & 31;
    if (l == 0) { sh0[w] = s; sh1[w] = s2; }
    __syncthreads();
    if (threadIdx.x == 0) {
        float ts = 0.f, ts2 = 0.f;
        #pragma unroll
        for (int i = 0; i < 8; i++) { ts += sh0[i]; ts2 += sh1[i]; }
        d_ps[(b * NBANDS + band) * NCH + ch] = make_float2(ts, ts2);
    }
}

// ---------------------------------------------------------------------------
// Stats stage 2: deterministic fp64 combine; fold GN into per-k affine A, B.
// ---------------------------------------------------------------------------
__global__ __launch_bounds__(64)
void stats2(const float* __restrict__ gnw, const float* __restrict__ gnb)
{
    const int b    = blockIdx.x;
    const int band = blockIdx.y;
    const int bw   = c_bw[band];
    const int n    = bw * NT * 2;

    __shared__ float sh_mean, sh_inv;
    if (threadIdx.x == 0) {
        double ts = 0.0, ts2 = 0.0;
        #pragma unroll
        for (int i = 0; i < NCH; i++) {
            float2 v = d_ps[(b * NBANDS + band) * NCH + i];
            ts += (double)v.x; ts2 += (double)v.y;
        }
        double mean = ts / n;
        double var  = ts2 / n - mean * mean;
        sh_mean = (float)mean;
        sh_inv  = rsqrtf((float)var + 1e-5f);
    }
    __syncthreads();

    const int c = 2 * bw;
    if (threadIdx.x < c) {
        float gw = gnw[band * MAXC + threadIdx.x];
        float gb = gnb[band * MAXC + threadIdx.x];
        float A  = gw * sh_inv;
        int   kg = c_kal[band] + threadIdx.x;
        d_A2[b * KTOT + kg] = A;
        d_B2[b * KTOT + kg] = gb - A * sh_mean;
    }
}

// ---------------------------------------------------------------------------
// Weight/bias prep, interleaved-o: row position 4l+j holds o = l + {0,64,32,96}[j].
// ---------------------------------------------------------------------------
__global__ __launch_bounds__(256)
void prep_w(const float* __restrict__ fcw, const float* __restrict__ fcb)
{
    const int band = blockIdx.x;
    const int C    = 2 * c_bw[band];
    const int kp   = (C + 3) & ~3;
    const int kal  = c_kal[band];
    for (int idx = threadIdx.x; idx < kp * NO; idx += blockDim.x) {
        const int k = idx >> 7;
        const int p = idx & 127;
        const int l = p >> 2;
        const int j = p & 3;
        const int o = l + (j & 1) * 64 + (j >> 1) * 32;   // {0,64,32,96}
        d_w2[(kal + k) * NO + p] = (k < C) ? fcw[(band * NO + o) * MAXC + k] : 0.0f;
    }
    if (threadIdx.x < NO) {
        const int p = threadIdx.x;
        const int l = p >> 2;
        const int j = p & 3;
        const int o = l + (j & 1) * 64 + (j >> 1) * 32;
        d_bp[band * NO + p] = fcb[band * NO + o];
    }
}

// ---------------------------------------------------------------------------
// Fused kernel, TT=4, occupancy 2 (phase overlap across the two resident
// blocks hides load latency). y duplicated {y,y} pairs for f32x2 broadcast;
// s_out in exact output order; final copy via cp.async.bulk smem -> gmem.
// ---------------------------------------------------------------------------
#define SOUT_F   (TT * OUTW)                  // 15872 floats (63488 B)
#define SY_F     (TT * KTOT * 2)              // 4288 floats
#define SMEM_F   (SOUT_F + SY_F + 2 * KTOT)   // 21232 floats = 84928 B

#define FMA2(acc, wv, yv) \
    asm("fma.rn.f32x2 %0, %1, %2, %0;" : "+l"(acc) : "l"(wv), "l"(yv));

__global__ __launch_bounds__(512, 2)
void fused_kernel(const float* __restrict__ x,
                  float* __restrict__ out)
{
    extern __shared__ float sm[];
    float* s_out = sm;                        // [t][OUTW] exact output order
    float* s_y2  = sm + SOUT_F;               // [t][KTOT] duplicated pairs
    float* s_A   = sm + SOUT_F + SY_F;
    float* s_B   = s_A + KTOT;

    const int b   = blockIdx.y;
    const int t0  = blockIdx.x * TT;
    const int tid = threadIdx.x;

    for (int i = tid; i < KTOT; i += 512) {
        s_A[i] = d_A2[b * KTOT + i];
        s_B[i] = d_B2[b * KTOT + i];
    }
    // zero only the 22 padded k-slots (w-pad is 0, but 0*uninit = NaN)
    if (tid < 22 * TT) {
        const int t    = tid / 22;
        const int slot = c_pad[tid - 22 * t];
        *(float2*)&s_y2[(t * KTOT + slot) * 2] = make_float2(0.f, 0.f);
    }
    __syncthreads();

    // y-build: y[t][kg] = A*x + B, duplicated pair written with one STS.64
    for (int idx = tid; idx < NF * 2; idx += 512) {
        const int f = idx >> 1;
        const int q = idx & 1;                // q=0 -> t0,t1 ; q=1 -> t2,t3
        const float4 v = *(const float4*)(x + ((size_t)(b * NF + f) * NT + t0) * 2 + q * 4);
        const int kg = kg_of_f(f);
        const int ta = 2 * q, tb = 2 * q + 1;
        const float A0 = s_A[kg], B0 = s_B[kg];
        const float A1 = s_A[kg + 1], B1 = s_B[kg + 1];
        float y;
        y = fmaf(A0, v.x, B0);
        *(float2*)&s_y2[(ta * KTOT + kg    ) * 2] = make_float2(y, y);
        y = fmaf(A1, v.y, B1);
        *(float2*)&s_y2[(ta * KTOT + kg + 1) * 2] = make_float2(y, y);
        y = fmaf(A0, v.z, B0);
        *(float2*)&s_y2[(tb * KTOT + kg    ) * 2] = make_float2(y, y);
        y = fmaf(A1, v.w, B1);
        *(float2*)&s_y2[(tb * KTOT + kg + 1) * 2] = make_float2(y, y);
    }
    __syncthreads();

    const int lane = tid & 31;
    const int warp = tid >> 5;     // = band group

    for (int bi = c_gs[warp]; bi < c_gs[warp + 1]; bi++) {
        const int band = c_gb[bi];
        const int kal  = c_kal[band];
        const int kcnt = (2 * c_bw[band] + 3) & ~3;
        const ulonglong2* wp = (const ulonglong2*)(d_w2 + (size_t)kal * NO) + lane;

        unsigned long long acc[TT][2];
        {
            ulonglong2 bz = __ldg((const ulonglong2*)(d_bp + band * NO) + lane);
            #pragma unroll
            for (int t = 0; t < TT; t++) { acc[t][0] = bz.x; acc[t][1] = bz.y; }
        }

        const unsigned long long* yb =
            (const unsigned long long*)s_y2 + kal;   // index: t*KTOT + k

        for (int k = 0; k < kcnt; k += 4) {
            const ulonglong2 w0 = __ldg(wp + (k + 0) * 32);
            const ulonglong2 w1 = __ldg(wp + (k + 1) * 32);
            const ulonglong2 w2 = __ldg(wp + (k + 2) * 32);
            const ulonglong2 w3 = __ldg(wp + (k + 3) * 32);
            #pragma unroll
            for (int t = 0; t < TT; t++) {
                const ulonglong2 ya = *(const ulonglong2*)(yb + t * KTOT + k);
                const ulonglong2 yc = *(const ulonglong2*)(yb + t * KTOT + k + 2);
                FMA2(acc[t][0], w0.x, ya.x) FMA2(acc[t][1], w0.y, ya.x)
                FMA2(acc[t][0], w1.x, ya.y) FMA2(acc[t][1], w1.y, ya.y)
                FMA2(acc[t][0], w2.x, yc.x) FMA2(acc[t][1], w2.y, yc.x)
                FMA2(acc[t][0], w3.x, yc.y) FMA2(acc[t][1], w3.y, yc.y)
            }
        }

        // conflict-free scalar STS: bank = (31*lane + band) mod 32 (distinct/lane)
        #pragma unroll
        for (int t = 0; t < TT; t++) {
            float* so = s_out + t * OUTW + 31 * lane + band;
            float2 pa = u2f(acc[t][0]);     // (o=l,    o=l+64)
            float2 pb = u2f(acc[t][1]);     // (o=l+32, o=l+96)
            so[0]    = pa.x;
            so[1984] = pa.y;                // 31*64
            so[992]  = pb.x;                // 31*32
            so[2976] = pb.y;                // 31*96
        }
    }
    __syncthreads();

    // async bulk copy smem -> gmem (contiguous 63488 B), issued by one thread
    if (tid == 0) {
        unsigned int saddr;
        asm("{ .reg .u64 t; cvta.to.shared.u64 t, %1; cvt.u32.u64 %0, t; }"
            : "=r"(saddr) : "l"(s_out));
        float* dst = out + (size_t)(b * NT + t0) * OUTW;
        asm volatile("fence.proxy.async.shared::cta;" ::: "memory");
        asm volatile("cp.async.bulk.global.shared::cta.bulk_group [%0], [%1], %2;"
                     :: "l"(dst), "r"(saddr), "r"(SOUT_F * 4) : "memory");
        asm volatile("cp.async.bulk.commit_group;" ::: "memory");
        asm volatile("cp.async.bulk.wait_group.read 0;" ::: "memory");
    }
}

// ---------------------------------------------------------------------------
extern "C" void kernel_launch(void* const* d_in, const int* in_sizes, int n_in,
                              void* d_out, int out_size)
{
    const float* x   = (const float*)d_in[0];
    const float* gnw = (const float*)d_in[1];
    const float* gnb = (const float*)d_in[2];
    const float* fcw = (const float*)d_in[3];
    const float* fcb = (const float*)d_in[4];
    float* out = (float*)d_out;

    const int smem_bytes = SMEM_F * 4;
    cudaFuncSetAttribute(fused_kernel,
                         cudaFuncAttributeMaxDynamicSharedMemorySize, smem_bytes);

    stats1<<<dim3(NB, NBANDS, NCH), 256>>>(x);
    stats2<<<dim3(NB, NBANDS), 64>>>(gnw, gnb);
    prep_w<<<NBANDS, 256>>>(fcw, fcb);
    fused_kernel<<<dim3(NT / TT, NB), 512, smem_bytes>>>(x, out);
}